// round 6
// baseline (speedup 1.0000x reference)
#include <cuda_runtime.h>
#include <cstdint>

#define NB 128
#define NT 512
#define NE 128
#define NK 4
#define NNEG 64
#define TILE 128
#define NTH 256
#define NWARP 8
#define POSW 16                   // positions per warp
#define NBLK (NB * (NT / TILE))   // 512 blocks

// smem layout (bytes)
#define NEGT_OFF 0                                 // [32 chunk][64 neg] u32 = 8KB
#define CEROW_OFF (32 * NNEG * 4)                  // 8192: per-warp ce row, 8 x 512B
#define SUM_OFF (CEROW_OFF + NWARP * 512)          // 12288
#define SMEM_BYTES (SUM_OFF + 32)

#define QI 25.4f          // 127/5
#define QS (5.0f / 127.0f)

__device__ double g_part[NBLK][NK];   // per-block partials (overwritten every replay)
__device__ unsigned int g_ctr;        // zero-init; last block resets each replay

__device__ __forceinline__ uint32_t q8(float v) {
    int q = __float2int_rn(v * QI);
    q = q > 127 ? 127 : q;
    q = q < -127 ? -127 : q;
    return (uint32_t)q & 255u;
}

__global__ __launch_bounds__(NTH, 4) void cpc_dp4a(
    const float* __restrict__ base,       // [B, T, E]
    const float* __restrict__ mc,         // [B, T, E, K]
    const int*   __restrict__ seq_lens,   // [B]
    const int*   __restrict__ sample_ids, // [B, NNEG]
    float* __restrict__ out, int out_size)
{
    extern __shared__ char smem[];
    const int bid  = blockIdx.x;
    const int b    = bid >> 2;                  // 4 tiles per b
    const int t0   = (bid & 3) * TILE;
    const int tid  = threadIdx.x;
    const int w    = tid >> 5;
    const int lane = tid & 31;
    const int seqlen = seq_lens[b];
    const double LOG65D = 4.174387269895637;
    const float  LOG65  = 4.17438727f;

    const bool heavy = (t0 < seqlen);

    if (!heavy) {
        if (tid == 0) {
            #pragma unroll
            for (int i = 0; i < NK; ++i) {
                int cnt = NT - 1 - i - t0;
                if (cnt > TILE) cnt = TILE;
                if (cnt < 0) cnt = 0;
                g_part[bid][i] = (double)cnt * LOG65D;
            }
        }
    } else {
        if (tid < NK) ((float*)(smem + SUM_OFF))[tid] = 0.f;

        // ---- Gather + quantize negatives, transposed: NEGT[m][n]
        for (int idx = tid; idx < NNEG * 32; idx += NTH) {
            int n = idx >> 5, m = idx & 31;
            float4 v = ((const float4*)(base + (size_t)sample_ids[b * NNEG + n] * NE))[m];
            uint32_t p = q8(v.x) | (q8(v.y) << 8) | (q8(v.z) << 16) | (q8(v.w) << 24);
            *(uint32_t*)(smem + NEGT_OFF + (m * NNEG + n) * 4) = p;
        }
        __syncthreads();

        const float4* mc4 = (const float4*)mc;
        const uint32_t sel1 = (lane & 1) ? 0x3715u : 0x6240u;
        const uint32_t sel2 = (lane & 2) ? 0x3276u : 0x5410u;
        const int2* negt2 = (const int2*)(smem + NEGT_OFF);
        uint32_t* cerow_w = (uint32_t*)(smem + CEROW_OFF + w * 512);
        const int4* crow  = (const int4*)(smem + CEROW_OFF + w * 512);
        const float S2 = QS * QS;

        float wsum[4] = {0.f, 0.f, 0.f, 0.f};

        // ---- Fused per-position loop (one warp = one position at a time)
        #pragma unroll 1
        for (int j = 0; j < POSW; ++j) {
            const int r = w + NWARP * j;
            const int s = t0 + r;

            if (s >= seqlen) {                    // warp-uniform
                #pragma unroll
                for (int i = 0; i < 4; ++i)
                    if (s < NT - 1 - i) wsum[i] += LOG65;
                continue;
            }

            // -- prologue: load ce (coalesced float4 over K), exact fp32 positives
            const float4* src  = mc4 + (size_t)(b * NT + s) * NE;
            const float*  brow = base + (size_t)(b * NT + s + 1) * NE + lane;
            float4 c[4];
            #pragma unroll
            for (int g = 0; g < 4; ++g) c[g] = src[lane + 32 * g];

            float pacc[4] = {0.f, 0.f, 0.f, 0.f};
            #pragma unroll
            for (int i = 0; i < 4; ++i) {
                if (s + 1 + i < NT) {             // warp-uniform guard
                    #pragma unroll
                    for (int g = 0; g < 4; ++g) {
                        float cv = (i == 0) ? c[g].x : (i == 1) ? c[g].y
                                 : (i == 2) ? c[g].z : c[g].w;
                        pacc[i] += cv * brow[(size_t)i * NE + 32 * g];
                    }
                }
            }
            #pragma unroll
            for (int i = 0; i < 4; ++i) {
                #pragma unroll
                for (int o = 16; o > 0; o >>= 1)
                    pacc[i] += __shfl_xor_sync(0xffffffffu, pacc[i], o);
            }                                      // all lanes hold pacc[i]

            // -- quantize + 4x4 byte transpose across lane quads -> per-warp smem row
            #pragma unroll
            for (int g = 0; g < 4; ++g) {
                uint32_t A  = q8(c[g].x) | (q8(c[g].y) << 8) |
                              (q8(c[g].z) << 16) | (q8(c[g].w) << 24);
                uint32_t X  = __shfl_xor_sync(0xffffffffu, A, 1);
                uint32_t Bt = __byte_perm(A, X, sel1);
                uint32_t Y  = __shfl_xor_sync(0xffffffffu, Bt, 2);
                uint32_t Wd = __byte_perm(Bt, Y, sel2);
                cerow_w[lane + 32 * g] = Wd;
            }
            __syncwarp();

            // -- negative logits: LDS.128 (ce broadcast) + LDS.64 (2 negs) + 8 dp4a
            int a00 = 0, a01 = 0, a10 = 0, a11 = 0, a20 = 0, a21 = 0, a30 = 0, a31 = 0;
            #pragma unroll
            for (int m = 0; m < 32; ++m) {
                int4 cw = crow[m];
                int2 gw = negt2[m * 32 + lane];
                a00 = __dp4a(cw.x, gw.x, a00); a01 = __dp4a(cw.x, gw.y, a01);
                a10 = __dp4a(cw.y, gw.x, a10); a11 = __dp4a(cw.y, gw.y, a11);
                a20 = __dp4a(cw.z, gw.x, a20); a21 = __dp4a(cw.z, gw.y, a21);
                a30 = __dp4a(cw.w, gw.x, a30); a31 = __dp4a(cw.w, gw.y, a31);
            }
            __syncwarp();                          // row buffer reuse next iteration

            int accs[4][2] = {{a00, a01}, {a10, a11}, {a20, a21}, {a30, a31}};

            // -- no-max softmax (logit range ~|70| << 88 overflow): direct expf sum
            #pragma unroll
            for (int i = 0; i < 4; ++i) {
                if (s < NT - 1 - i) {              // warp-uniform
                    float se = __expf((float)accs[i][0] * S2) +
                               __expf((float)accs[i][1] * S2);
                    #pragma unroll
                    for (int o = 16; o > 0; o >>= 1)
                        se += __shfl_xor_sync(0xffffffffu, se, o);
                    se += __expf(pacc[i]);
                    wsum[i] += __logf(se) - pacc[i];
                }
            }
        }

        if (lane == 0) {
            #pragma unroll
            for (int i = 0; i < NK; ++i)
                atomicAdd((float*)(smem + SUM_OFF) + i, wsum[i]);
        }
        __syncthreads();
        if (tid < NK)
            g_part[bid][tid] = (double)((float*)(smem + SUM_OFF))[tid];
    }

    // ---- Last block finalizes
    __threadfence();
    __shared__ unsigned int s_last;
    if (tid == 0) s_last = (atomicAdd(&g_ctr, 1u) == (unsigned)(NBLK - 1));
    __syncthreads();
    if (!s_last) return;

    __shared__ double ssum[NK];
    if (tid < NK) ssum[tid] = 0.0;
    __syncthreads();

    double acc[NK] = {0.0, 0.0, 0.0, 0.0};
    for (int r = tid; r < NBLK; r += NTH) {
        #pragma unroll
        for (int i = 0; i < NK; ++i) acc[i] += g_part[r][i];
    }
    #pragma unroll
    for (int i = 0; i < NK; ++i) {
        #pragma unroll
        for (int o = 16; o > 0; o >>= 1)
            acc[i] += __shfl_xor_sync(0xffffffffu, acc[i], o);
    }
    if (lane == 0) {
        #pragma unroll
        for (int i = 0; i < NK; ++i) atomicAdd(&ssum[i], acc[i]);
    }
    __syncthreads();

    if (tid == 0) {
        double t = 0.0;
        #pragma unroll
        for (int i = 0; i < NK; ++i)
            t += ssum[i] / ((double)NB * (double)(NT - (i + 1)));
        out[0] = (float)(t / NK);
        g_ctr = 0;                      // reset for next replay
    }
    for (int j = tid + 1; j < out_size; j += NTH) out[j] = out[0];
}

extern "C" void kernel_launch(void* const* d_in, const int* in_sizes, int n_in,
                              void* d_out, int out_size) {
    const float* base = (const float*)d_in[0];
    const float* mc   = (const float*)d_in[1];
    const int*   seq  = (const int*)d_in[2];
    const int*   sid  = (const int*)d_in[3];

    cudaFuncSetAttribute(cpc_dp4a, cudaFuncAttributeMaxDynamicSharedMemorySize, SMEM_BYTES);

    cpc_dp4a<<<NBLK, NTH, SMEM_BYTES>>>(base, mc, seq, sid, (float*)d_out, out_size);
}

// round 7
// speedup vs baseline: 1.2772x; 1.2772x over previous
#include <cuda_runtime.h>
#include <cstdint>

#define NB 128
#define NT 512
#define NE 128
#define NK 4
#define NNEG 64
#define TILE 32
#define NTH 256
#define NWARP 8
#define POSW (TILE / NWARP)       // 4 positions per warp
#define TPB (NT / TILE)           // 16 tiles per batch row
#define NBLK (NB * TPB)           // 2048 blocks

// smem layout (bytes)
#define NEGT_OFF 0                                 // [32 chunk][64 neg] u32 = 8KB
#define CEROW_OFF (32 * NNEG * 4)                  // 8192: per-warp ce row, 8 x 512B
#define SUM_OFF (CEROW_OFF + NWARP * 512)          // 12288
#define SMEM_BYTES (SUM_OFF + 32)

#define QI 25.4f          // 127/5
#define QS (5.0f / 127.0f)

__device__ double g_part[NBLK][NK];   // per-block partials (overwritten every replay)
__device__ unsigned int g_ctr;        // zero-init; last block resets each replay

__device__ __forceinline__ uint32_t q8(float v) {
    int q = __float2int_rn(v * QI);
    q = q > 127 ? 127 : q;
    q = q < -127 ? -127 : q;
    return (uint32_t)q & 255u;
}

__global__ __launch_bounds__(NTH, 4) void cpc_dp4a(
    const float* __restrict__ base,       // [B, T, E]
    const float* __restrict__ mc,         // [B, T, E, K]
    const int*   __restrict__ seq_lens,   // [B]
    const int*   __restrict__ sample_ids, // [B, NNEG]
    float* __restrict__ out, int out_size)
{
    extern __shared__ char smem[];
    const int bid  = blockIdx.x;
    const int b    = bid >> 4;                  // 16 tiles per b
    const int t0   = (bid & 15) * TILE;
    const int tid  = threadIdx.x;
    const int w    = tid >> 5;
    const int lane = tid & 31;
    const int seqlen = seq_lens[b];
    const double LOG65D = 4.174387269895637;
    const float  LOG65  = 4.17438727f;

    const bool heavy = (t0 < seqlen);

    if (!heavy) {
        // Fully masked tile: every valid position contributes exactly log(65).
        if (tid == 0) {
            #pragma unroll
            for (int i = 0; i < NK; ++i) {
                int cnt = NT - 1 - i - t0;
                if (cnt > TILE) cnt = TILE;
                if (cnt < 0) cnt = 0;
                g_part[bid][i] = (double)cnt * LOG65D;
            }
        }
    } else {
        if (tid < NK) ((float*)(smem + SUM_OFF))[tid] = 0.f;

        // ---- Gather + quantize negatives, transposed: NEGT[m][n] (L2-resident)
        for (int idx = tid; idx < NNEG * 32; idx += NTH) {
            int n = idx >> 5, m = idx & 31;
            float4 v = ((const float4*)(base + (size_t)sample_ids[b * NNEG + n] * NE))[m];
            uint32_t p = q8(v.x) | (q8(v.y) << 8) | (q8(v.z) << 16) | (q8(v.w) << 24);
            *(uint32_t*)(smem + NEGT_OFF + (m * NNEG + n) * 4) = p;
        }
        __syncthreads();

        const float4* mc4 = (const float4*)mc;
        const uint32_t sel1 = (lane & 1) ? 0x3715u : 0x6240u;
        const uint32_t sel2 = (lane & 2) ? 0x3276u : 0x5410u;
        const int2* negt2 = (const int2*)(smem + NEGT_OFF);
        uint32_t* cerow_w = (uint32_t*)(smem + CEROW_OFF + w * 512);
        const int4* crow  = (const int4*)(smem + CEROW_OFF + w * 512);
        const float S2 = QS * QS;

        float wsum[4] = {0.f, 0.f, 0.f, 0.f};

        // ---- Fused per-position loop (warp w owns positions t0 + w + 8*j)
        #pragma unroll 1
        for (int j = 0; j < POSW; ++j) {
            const int r = w + NWARP * j;
            const int s = t0 + r;

            if (s >= seqlen) {                    // warp-uniform
                #pragma unroll
                for (int i = 0; i < 4; ++i)
                    if (s < NT - 1 - i) wsum[i] += LOG65;
                continue;
            }

            // -- prologue: coalesced float4 loads over K; exact fp32 positives
            const float4* src  = mc4 + (size_t)(b * NT + s) * NE;
            const float*  brow = base + (size_t)(b * NT + s + 1) * NE + lane;
            float4 c[4];
            #pragma unroll
            for (int g = 0; g < 4; ++g) c[g] = src[lane + 32 * g];

            float pacc[4] = {0.f, 0.f, 0.f, 0.f};
            #pragma unroll
            for (int i = 0; i < 4; ++i) {
                if (s + 1 + i < NT) {             // warp-uniform guard
                    #pragma unroll
                    for (int g = 0; g < 4; ++g) {
                        float cv = (i == 0) ? c[g].x : (i == 1) ? c[g].y
                                 : (i == 2) ? c[g].z : c[g].w;
                        pacc[i] += cv * brow[(size_t)i * NE + 32 * g];
                    }
                }
            }
            #pragma unroll
            for (int i = 0; i < 4; ++i) {
                #pragma unroll
                for (int o = 16; o > 0; o >>= 1)
                    pacc[i] += __shfl_xor_sync(0xffffffffu, pacc[i], o);
            }                                      // all lanes hold pacc[i]

            // -- quantize + 4x4 byte transpose across lane quads -> per-warp smem row
            #pragma unroll
            for (int g = 0; g < 4; ++g) {
                uint32_t A  = q8(c[g].x) | (q8(c[g].y) << 8) |
                              (q8(c[g].z) << 16) | (q8(c[g].w) << 24);
                uint32_t X  = __shfl_xor_sync(0xffffffffu, A, 1);
                uint32_t Bt = __byte_perm(A, X, sel1);
                uint32_t Y  = __shfl_xor_sync(0xffffffffu, Bt, 2);
                uint32_t Wd = __byte_perm(Bt, Y, sel2);
                cerow_w[lane + 32 * g] = Wd;
            }
            __syncwarp();

            // -- negative logits: LDS.128 (ce broadcast) + LDS.64 (2 negs) + 8 dp4a
            int a00 = 0, a01 = 0, a10 = 0, a11 = 0, a20 = 0, a21 = 0, a30 = 0, a31 = 0;
            #pragma unroll
            for (int m = 0; m < 32; ++m) {
                int4 cw = crow[m];
                int2 gw = negt2[m * 32 + lane];
                a00 = __dp4a(cw.x, gw.x, a00); a01 = __dp4a(cw.x, gw.y, a01);
                a10 = __dp4a(cw.y, gw.x, a10); a11 = __dp4a(cw.y, gw.y, a11);
                a20 = __dp4a(cw.z, gw.x, a20); a21 = __dp4a(cw.z, gw.y, a21);
                a30 = __dp4a(cw.w, gw.x, a30); a31 = __dp4a(cw.w, gw.y, a31);
            }
            __syncwarp();                          // row buffer reused next iteration

            int accs[4][2] = {{a00, a01}, {a10, a11}, {a20, a21}, {a30, a31}};

            // -- no-max softmax (|logit| << 88): direct expf sum is safe
            #pragma unroll
            for (int i = 0; i < 4; ++i) {
                if (s < NT - 1 - i) {              // warp-uniform
                    float se = __expf((float)accs[i][0] * S2) +
                               __expf((float)accs[i][1] * S2);
                    #pragma unroll
                    for (int o = 16; o > 0; o >>= 1)
                        se += __shfl_xor_sync(0xffffffffu, se, o);
                    se += __expf(pacc[i]);
                    wsum[i] += __logf(se) - pacc[i];
                }
            }
        }

        if (lane == 0) {
            #pragma unroll
            for (int i = 0; i < NK; ++i)
                atomicAdd((float*)(smem + SUM_OFF) + i, wsum[i]);
        }
        __syncthreads();
        if (tid < NK)
            g_part[bid][tid] = (double)((float*)(smem + SUM_OFF))[tid];
    }

    // ---- Last block finalizes
    __threadfence();
    __shared__ unsigned int s_last;
    if (tid == 0) s_last = (atomicAdd(&g_ctr, 1u) == (unsigned)(NBLK - 1));
    __syncthreads();
    if (!s_last) return;

    __shared__ double ssum[NK];
    if (tid < NK) ssum[tid] = 0.0;
    __syncthreads();

    double acc[NK] = {0.0, 0.0, 0.0, 0.0};
    for (int r = tid; r < NBLK; r += NTH) {
        #pragma unroll
        for (int i = 0; i < NK; ++i) acc[i] += g_part[r][i];
    }
    #pragma unroll
    for (int i = 0; i < NK; ++i) {
        #pragma unroll
        for (int o = 16; o > 0; o >>= 1)
            acc[i] += __shfl_xor_sync(0xffffffffu, acc[i], o);
    }
    if (lane == 0) {
        #pragma unroll
        for (int i = 0; i < NK; ++i) atomicAdd(&ssum[i], acc[i]);
    }
    __syncthreads();

    if (tid == 0) {
        double t = 0.0;
        #pragma unroll
        for (int i = 0; i < NK; ++i)
            t += ssum[i] / ((double)NB * (double)(NT - (i + 1)));
        out[0] = (float)(t / NK);
        g_ctr = 0;                      // reset for next replay
    }
    for (int j = tid + 1; j < out_size; j += NTH) out[j] = out[0];
}

extern "C" void kernel_launch(void* const* d_in, const int* in_sizes, int n_in,
                              void* d_out, int out_size) {
    const float* base = (const float*)d_in[0];
    const float* mc   = (const float*)d_in[1];
    const int*   seq  = (const int*)d_in[2];
    const int*   sid  = (const int*)d_in[3];

    cudaFuncSetAttribute(cpc_dp4a, cudaFuncAttributeMaxDynamicSharedMemorySize, SMEM_BYTES);

    cpc_dp4a<<<NBLK, NTH, SMEM_BYTES>>>(base, mc, seq, sid, (float*)d_out, out_size);
}

// round 8
// speedup vs baseline: 1.2936x; 1.0129x over previous
#include <cuda_runtime.h>
#include <cstdint>

#define NB 128
#define NT 512
#define NE 128
#define NK 4
#define NNEG 64
#define TILE 32
#define NTH 256
#define NWARP 8
#define TPB (NT / TILE)           // 16 tiles per batch row
#define NBLK (NB * TPB)           // 2048 blocks

// smem layout (bytes)
#define NEGT_OFF 0                                 // [32 chunk][64 neg] u32 = 8KB
#define CEROW_OFF (32 * NNEG * 4)                  // 8192: 16 rows (8 warps x 2) x 512B
#define SUM_OFF (CEROW_OFF + NWARP * 2 * 512)      // 16384
#define SMEM_BYTES (SUM_OFF + 32)

#define QI 25.4f          // 127/5
#define QS (5.0f / 127.0f)

__device__ double g_part[NBLK][NK];   // per-block partials (overwritten every replay)
__device__ unsigned int g_ctr;        // zero-init; last block resets each replay

__device__ __forceinline__ uint32_t q8(float v) {
    int q = __float2int_rn(v * QI);
    q = q > 127 ? 127 : q;
    q = q < -127 ? -127 : q;
    return (uint32_t)q & 255u;
}

__global__ __launch_bounds__(NTH, 4) void cpc_dp4a(
    const float* __restrict__ base,       // [B, T, E]
    const float* __restrict__ mc,         // [B, T, E, K]
    const int*   __restrict__ seq_lens,   // [B]
    const int*   __restrict__ sample_ids, // [B, NNEG]
    float* __restrict__ out, int out_size)
{
    extern __shared__ char smem[];
    const int bid  = blockIdx.x;
    const int b    = bid >> 4;                  // 16 tiles per b
    const int t0   = (bid & 15) * TILE;
    const int tid  = threadIdx.x;
    const int w    = tid >> 5;
    const int lane = tid & 31;
    const int seqlen = seq_lens[b];
    const double LOG65D = 4.174387269895637;
    const float  LOG65  = 4.17438727f;

    const bool heavy = (t0 < seqlen);

    if (!heavy) {
        // Fully masked tile: every valid position contributes exactly log(65).
        if (tid == 0) {
            #pragma unroll
            for (int i = 0; i < NK; ++i) {
                int cnt = NT - 1 - i - t0;
                if (cnt > TILE) cnt = TILE;
                if (cnt < 0) cnt = 0;
                g_part[bid][i] = (double)cnt * LOG65D;
            }
        }
    } else {
        if (tid < NK) ((float*)(smem + SUM_OFF))[tid] = 0.f;

        // ---- Gather + quantize negatives: NEGT[m][n] = negative n, e in [4m, 4m+4)
        for (int idx = tid; idx < NNEG * 32; idx += NTH) {
            int n = idx >> 5, m = idx & 31;
            float4 v = ((const float4*)(base + (size_t)sample_ids[b * NNEG + n] * NE))[m];
            uint32_t p = q8(v.x) | (q8(v.y) << 8) | (q8(v.z) << 16) | (q8(v.w) << 24);
            *(uint32_t*)(smem + NEGT_OFF + (m * NNEG + n) * 4) = p;
        }
        __syncthreads();

        const float4* mc4 = (const float4*)mc;
        const int2* negt2 = (const int2*)(smem + NEGT_OFF);
        int4* rowA = (int4*)(smem + CEROW_OFF + (w * 2 + 0) * 512);
        int4* rowB = (int4*)(smem + CEROW_OFF + (w * 2 + 1) * 512);
        const float S2 = QS * QS;

        float wsum[4] = {0.f, 0.f, 0.f, 0.f};

        // Prologue for one position: e-contiguous layout (lane owns e = 4*lane+k).
        // Fills its chunk's 4 dp4a words locally (no cross-lane transpose) and
        // computes exact fp32 positives (butterfly -> all lanes).
        auto prep = [&](int s, int4* row, float* pacc) {
            const float4* src = mc4 + (size_t)(b * NT + s) * NE + 4 * lane;
            float4 c0 = src[0], c1 = src[1], c2 = src[2], c3 = src[3];

            const float4* bp = (const float4*)(base + (size_t)(b * NT + s + 1) * NE) + lane;
            pacc[0] = pacc[1] = pacc[2] = pacc[3] = 0.f;
            #pragma unroll
            for (int i = 0; i < 4; ++i) {
                if (s + 1 + i < NT) {            // warp-uniform guard
                    float4 bv = bp[(size_t)i * 32];
                    float x0 = (i == 0) ? c0.x : (i == 1) ? c0.y : (i == 2) ? c0.z : c0.w;
                    float x1 = (i == 0) ? c1.x : (i == 1) ? c1.y : (i == 2) ? c1.z : c1.w;
                    float x2 = (i == 0) ? c2.x : (i == 1) ? c2.y : (i == 2) ? c2.z : c2.w;
                    float x3 = (i == 0) ? c3.x : (i == 1) ? c3.y : (i == 2) ? c3.z : c3.w;
                    pacc[i] = x0 * bv.x + x1 * bv.y + x2 * bv.z + x3 * bv.w;
                }
            }
            #pragma unroll
            for (int i = 0; i < 4; ++i) {
                #pragma unroll
                for (int o = 16; o > 0; o >>= 1)
                    pacc[i] += __shfl_xor_sync(0xffffffffu, pacc[i], o);
            }

            int4 wd;
            wd.x = (int)(q8(c0.x) | (q8(c1.x) << 8) | (q8(c2.x) << 16) | (q8(c3.x) << 24));
            wd.y = (int)(q8(c0.y) | (q8(c1.y) << 8) | (q8(c2.y) << 16) | (q8(c3.y) << 24));
            wd.z = (int)(q8(c0.z) | (q8(c1.z) << 8) | (q8(c2.z) << 16) | (q8(c3.z) << 24));
            wd.w = (int)(q8(c0.w) | (q8(c1.w) << 8) | (q8(c2.w) << 16) | (q8(c3.w) << 24));
            row[lane] = wd;                       // STS.128: steps 0..3 of chunk `lane`
        };

        // Per-position softmax epilogue (no-max: |logit| << 88 so expf is safe)
        auto finish = [&](int s, const int* acc, const float* pacc) {
            #pragma unroll
            for (int i = 0; i < 4; ++i) {
                if (s < NT - 1 - i) {             // warp-uniform
                    float se = __expf((float)acc[2 * i] * S2) +
                               __expf((float)acc[2 * i + 1] * S2);
                    #pragma unroll
                    for (int o = 16; o > 0; o >>= 1)
                        se += __shfl_xor_sync(0xffffffffu, se, o);
                    se += __expf(pacc[i]);
                    wsum[i] += __logf(se) - pacc[i];
                }
            }
        };

        #pragma unroll 1
        for (int jp = 0; jp < 2; ++jp) {
            const int sA = t0 + w + 8 * jp;       // warp-uniform pair (sA, sA+16)
            const int sB = sA + 16;
            const bool mA = (sA < seqlen);
            const bool mB = (sB < seqlen);        // mB implies mA

            if (!mA) {                            // both masked
                #pragma unroll
                for (int i = 0; i < 4; ++i) {
                    if (sA < NT - 1 - i) wsum[i] += LOG65;
                    if (sB < NT - 1 - i) wsum[i] += LOG65;
                }
                continue;
            }

            float paccA[4], paccB[4];
            prep(sA, rowA, paccA);
            if (mB) prep(sB, rowB, paccB);
            __syncwarp();

            // Joint dp4a loop: shared gw load, 16 independent accumulator chains
            int aA[8] = {0, 0, 0, 0, 0, 0, 0, 0};
            int aB[8] = {0, 0, 0, 0, 0, 0, 0, 0};
            #pragma unroll
            for (int m = 0; m < 32; ++m) {
                int4 cwA = rowA[m];                       // broadcast LDS.128
                int4 cwB = rowB[m];                       // broadcast LDS.128
                int2 gw  = negt2[m * 32 + lane];          // conflict-free LDS.64
                aA[0] = __dp4a(cwA.x, gw.x, aA[0]); aA[1] = __dp4a(cwA.x, gw.y, aA[1]);
                aA[2] = __dp4a(cwA.y, gw.x, aA[2]); aA[3] = __dp4a(cwA.y, gw.y, aA[3]);
                aA[4] = __dp4a(cwA.z, gw.x, aA[4]); aA[5] = __dp4a(cwA.z, gw.y, aA[5]);
                aA[6] = __dp4a(cwA.w, gw.x, aA[6]); aA[7] = __dp4a(cwA.w, gw.y, aA[7]);
                aB[0] = __dp4a(cwB.x, gw.x, aB[0]); aB[1] = __dp4a(cwB.x, gw.y, aB[1]);
                aB[2] = __dp4a(cwB.y, gw.x, aB[2]); aB[3] = __dp4a(cwB.y, gw.y, aB[3]);
                aB[4] = __dp4a(cwB.z, gw.x, aB[4]); aB[5] = __dp4a(cwB.z, gw.y, aB[5]);
                aB[6] = __dp4a(cwB.w, gw.x, aB[6]); aB[7] = __dp4a(cwB.w, gw.y, aB[7]);
            }
            __syncwarp();                          // rows reused next iteration

            finish(sA, aA, paccA);
            if (mB) {
                finish(sB, aB, paccB);
            } else {
                #pragma unroll
                for (int i = 0; i < 4; ++i)
                    if (sB < NT - 1 - i) wsum[i] += LOG65;
            }
        }

        if (lane == 0) {
            #pragma unroll
            for (int i = 0; i < NK; ++i)
                atomicAdd((float*)(smem + SUM_OFF) + i, wsum[i]);
        }
        __syncthreads();
        if (tid < NK)
            g_part[bid][tid] = (double)((float*)(smem + SUM_OFF))[tid];
    }

    // ---- Last block finalizes
    __threadfence();
    __shared__ unsigned int s_last;
    if (tid == 0) s_last = (atomicAdd(&g_ctr, 1u) == (unsigned)(NBLK - 1));
    __syncthreads();
    if (!s_last) return;

    __shared__ double ssum[NK];
    if (tid < NK) ssum[tid] = 0.0;
    __syncthreads();

    double acc[NK] = {0.0, 0.0, 0.0, 0.0};
    for (int r = tid; r < NBLK; r += NTH) {
        #pragma unroll
        for (int i = 0; i < NK; ++i) acc[i] += g_part[r][i];
    }
    #pragma unroll
    for (int i = 0; i < NK; ++i) {
        #pragma unroll
        for (int o = 16; o > 0; o >>= 1)
            acc[i] += __shfl_xor_sync(0xffffffffu, acc[i], o);
    }
    if (lane == 0) {
        #pragma unroll
        for (int i = 0; i < NK; ++i) atomicAdd(&ssum[i], acc[i]);
    }
    __syncthreads();

    if (tid == 0) {
        double t = 0.0;
        #pragma unroll
        for (int i = 0; i < NK; ++i)
            t += ssum[i] / ((double)NB * (double)(NT - (i + 1)));
        out[0] = (float)(t / NK);
        g_ctr = 0;                      // reset for next replay
    }
    for (int j = tid + 1; j < out_size; j += NTH) out[j] = out[0];
}

extern "C" void kernel_launch(void* const* d_in, const int* in_sizes, int n_in,
                              void* d_out, int out_size) {
    const float* base = (const float*)d_in[0];
    const float* mc   = (const float*)d_in[1];
    const int*   seq  = (const int*)d_in[2];
    const int*   sid  = (const int*)d_in[3];

    cudaFuncSetAttribute(cpc_dp4a, cudaFuncAttributeMaxDynamicSharedMemorySize, SMEM_BYTES);

    cpc_dp4a<<<NBLK, NTH, SMEM_BYTES>>>(base, mc, seq, sid, (float*)d_out, out_size);
}

// round 9
// speedup vs baseline: 1.2996x; 1.0046x over previous
#include <cuda_runtime.h>
#include <cstdint>

#define NB 128
#define NT 512
#define NE 128
#define NK 4
#define NNEG 64
#define TILE 32
#define NTH 256
#define NWARP 8
#define TPB (NT / TILE)           // 16 tiles per batch row
#define NBLK (NB * TPB)           // 2048 blocks

// smem layout (bytes)
#define NEGT_OFF 0                                 // [32 chunk][64 neg] u32 = 8KB
#define CEROW_OFF (32 * NNEG * 4)                  // 8192: 16 rows (8 warps x 2) x 512B
#define SUM_OFF (CEROW_OFF + NWARP * 2 * 512)      // 16384
#define SMEM_BYTES (SUM_OFF + 32)

#define QI 25.4f          // 127/5
#define QS (5.0f / 127.0f)

__device__ double g_part[NBLK][NK];   // per-block partials (overwritten every replay)
__device__ unsigned int g_ctr;        // zero-init; last block resets each replay

__device__ __forceinline__ uint32_t q8(float v) {
    int q = __float2int_rn(v * QI);
    q = q > 127 ? 127 : q;
    q = q < -127 ? -127 : q;
    return (uint32_t)q & 255u;
}

__global__ __launch_bounds__(NTH, 4) void cpc_dp4a(
    const float* __restrict__ base,       // [B, T, E]
    const float* __restrict__ mc,         // [B, T, E, K]
    const int*   __restrict__ seq_lens,   // [B]
    const int*   __restrict__ sample_ids, // [B, NNEG]
    float* __restrict__ out, int out_size)
{
    extern __shared__ char smem[];
    const int bid  = blockIdx.x;
    // LPT mapping: tile-major. First-launched blocks are the (nearly always
    // heavy) low tiles of EVERY b; high tiles (mostly light) backfill the tail.
    const int b    = bid & (NB - 1);
    const int t0   = (bid >> 7) * TILE;
    const int tid  = threadIdx.x;
    const int w    = tid >> 5;
    const int lane = tid & 31;
    const int seqlen = seq_lens[b];
    const double LOG65D = 4.174387269895637;
    const float  LOG65  = 4.17438727f;

    const bool heavy = (t0 < seqlen);

    if (!heavy) {
        // Fully masked tile: every valid position contributes exactly log(65).
        if (tid == 0) {
            #pragma unroll
            for (int i = 0; i < NK; ++i) {
                int cnt = NT - 1 - i - t0;
                if (cnt > TILE) cnt = TILE;
                if (cnt < 0) cnt = 0;
                g_part[bid][i] = (double)cnt * LOG65D;
            }
        }
    } else {
        if (tid < NK) ((float*)(smem + SUM_OFF))[tid] = 0.f;

        // ---- Gather + quantize negatives: NEGT[m][n] = negative n, e in [4m, 4m+4)
        for (int idx = tid; idx < NNEG * 32; idx += NTH) {
            int n = idx >> 5, m = idx & 31;
            float4 v = ((const float4*)(base + (size_t)sample_ids[b * NNEG + n] * NE))[m];
            uint32_t p = q8(v.x) | (q8(v.y) << 8) | (q8(v.z) << 16) | (q8(v.w) << 24);
            *(uint32_t*)(smem + NEGT_OFF + (m * NNEG + n) * 4) = p;
        }
        __syncthreads();

        const float4* mc4 = (const float4*)mc;
        const int2* negt2 = (const int2*)(smem + NEGT_OFF);
        int4* rowA = (int4*)(smem + CEROW_OFF + (w * 2 + 0) * 512);
        int4* rowB = (int4*)(smem + CEROW_OFF + (w * 2 + 1) * 512);
        const float S2 = QS * QS;

        float wsum[4] = {0.f, 0.f, 0.f, 0.f};

        // Prologue for one position: e-contiguous layout (lane owns e = 4*lane+k).
        auto prep = [&](int s, int4* row, float* pacc) {
            const float4* src = mc4 + (size_t)(b * NT + s) * NE + 4 * lane;
            float4 c0 = src[0], c1 = src[1], c2 = src[2], c3 = src[3];

            const float4* bp = (const float4*)(base + (size_t)(b * NT + s + 1) * NE) + lane;
            pacc[0] = pacc[1] = pacc[2] = pacc[3] = 0.f;
            #pragma unroll
            for (int i = 0; i < 4; ++i) {
                if (s + 1 + i < NT) {            // warp-uniform guard
                    float4 bv = bp[(size_t)i * 32];
                    float x0 = (i == 0) ? c0.x : (i == 1) ? c0.y : (i == 2) ? c0.z : c0.w;
                    float x1 = (i == 0) ? c1.x : (i == 1) ? c1.y : (i == 2) ? c1.z : c1.w;
                    float x2 = (i == 0) ? c2.x : (i == 1) ? c2.y : (i == 2) ? c2.z : c2.w;
                    float x3 = (i == 0) ? c3.x : (i == 1) ? c3.y : (i == 2) ? c3.z : c3.w;
                    pacc[i] = x0 * bv.x + x1 * bv.y + x2 * bv.z + x3 * bv.w;
                }
            }
            #pragma unroll
            for (int i = 0; i < 4; ++i) {
                #pragma unroll
                for (int o = 16; o > 0; o >>= 1)
                    pacc[i] += __shfl_xor_sync(0xffffffffu, pacc[i], o);
            }

            int4 wd;
            wd.x = (int)(q8(c0.x) | (q8(c1.x) << 8) | (q8(c2.x) << 16) | (q8(c3.x) << 24));
            wd.y = (int)(q8(c0.y) | (q8(c1.y) << 8) | (q8(c2.y) << 16) | (q8(c3.y) << 24));
            wd.z = (int)(q8(c0.z) | (q8(c1.z) << 8) | (q8(c2.z) << 16) | (q8(c3.z) << 24));
            wd.w = (int)(q8(c0.w) | (q8(c1.w) << 8) | (q8(c2.w) << 16) | (q8(c3.w) << 24));
            row[lane] = wd;                       // STS.128: steps 0..3 of chunk `lane`
        };

        // Per-position softmax epilogue (no-max: |logit| << 88 so expf is safe)
        auto finish = [&](int s, const int* acc, const float* pacc) {
            #pragma unroll
            for (int i = 0; i < 4; ++i) {
                if (s < NT - 1 - i) {             // warp-uniform
                    float se = __expf((float)acc[2 * i] * S2) +
                               __expf((float)acc[2 * i + 1] * S2);
                    #pragma unroll
                    for (int o = 16; o > 0; o >>= 1)
                        se += __shfl_xor_sync(0xffffffffu, se, o);
                    se += __expf(pacc[i]);
                    wsum[i] += __logf(se) - pacc[i];
                }
            }
        };

        #pragma unroll 1
        for (int jp = 0; jp < 2; ++jp) {
            const int sA = t0 + w + 8 * jp;       // warp-uniform pair (sA, sA+16)
            const int sB = sA + 16;
            const bool mA = (sA < seqlen);
            const bool mB = (sB < seqlen);        // mB implies mA

            if (!mA) {                            // both masked
                #pragma unroll
                for (int i = 0; i < 4; ++i) {
                    if (sA < NT - 1 - i) wsum[i] += LOG65;
                    if (sB < NT - 1 - i) wsum[i] += LOG65;
                }
                continue;
            }

            float paccA[4], paccB[4];
            prep(sA, rowA, paccA);
            if (mB) prep(sB, rowB, paccB);
            __syncwarp();

            // Joint dp4a loop: shared gw load, 16 independent accumulator chains
            int aA[8] = {0, 0, 0, 0, 0, 0, 0, 0};
            int aB[8] = {0, 0, 0, 0, 0, 0, 0, 0};
            #pragma unroll
            for (int m = 0; m < 32; ++m) {
                int4 cwA = rowA[m];                       // broadcast LDS.128
                int4 cwB = rowB[m];                       // broadcast LDS.128
                int2 gw  = negt2[m * 32 + lane];          // conflict-free LDS.64
                aA[0] = __dp4a(cwA.x, gw.x, aA[0]); aA[1] = __dp4a(cwA.x, gw.y, aA[1]);
                aA[2] = __dp4a(cwA.y, gw.x, aA[2]); aA[3] = __dp4a(cwA.y, gw.y, aA[3]);
                aA[4] = __dp4a(cwA.z, gw.x, aA[4]); aA[5] = __dp4a(cwA.z, gw.y, aA[5]);
                aA[6] = __dp4a(cwA.w, gw.x, aA[6]); aA[7] = __dp4a(cwA.w, gw.y, aA[7]);
                aB[0] = __dp4a(cwB.x, gw.x, aB[0]); aB[1] = __dp4a(cwB.x, gw.y, aB[1]);
                aB[2] = __dp4a(cwB.y, gw.x, aB[2]); aB[3] = __dp4a(cwB.y, gw.y, aB[3]);
                aB[4] = __dp4a(cwB.z, gw.x, aB[4]); aB[5] = __dp4a(cwB.z, gw.y, aB[5]);
                aB[6] = __dp4a(cwB.w, gw.x, aB[6]); aB[7] = __dp4a(cwB.w, gw.y, aB[7]);
            }
            __syncwarp();                          // rows reused next iteration

            finish(sA, aA, paccA);
            if (mB) {
                finish(sB, aB, paccB);
            } else {
                #pragma unroll
                for (int i = 0; i < 4; ++i)
                    if (sB < NT - 1 - i) wsum[i] += LOG65;
            }
        }

        if (lane == 0) {
            #pragma unroll
            for (int i = 0; i < NK; ++i)
                atomicAdd((float*)(smem + SUM_OFF) + i, wsum[i]);
        }
        __syncthreads();
        if (tid < NK)
            g_part[bid][tid] = (double)((float*)(smem + SUM_OFF))[tid];
    }

    // ---- Last block finalizes
    __threadfence();
    __shared__ unsigned int s_last;
    if (tid == 0) s_last = (atomicAdd(&g_ctr, 1u) == (unsigned)(NBLK - 1));
    __syncthreads();
    if (!s_last) return;

    __shared__ double ssum[NK];
    if (tid < NK) ssum[tid] = 0.0;
    __syncthreads();

    double acc[NK] = {0.0, 0.0, 0.0, 0.0};
    for (int r = tid; r < NBLK; r += NTH) {
        #pragma unroll
        for (int i = 0; i < NK; ++i) acc[i] += g_part[r][i];
    }
    #pragma unroll
    for (int i = 0; i < NK; ++i) {
        #pragma unroll
        for (int o = 16; o > 0; o >>= 1)
            acc[i] += __shfl_xor_sync(0xffffffffu, acc[i], o);
    }
    if (lane == 0) {
        #pragma unroll
        for (int i = 0; i < NK; ++i) atomicAdd(&ssum[i], acc[i]);
    }
    __syncthreads();

    if (tid == 0) {
        double t = 0.0;
        #pragma unroll
        for (int i = 0; i < NK; ++i)
            t += ssum[i] / ((double)NB * (double)(NT - (i + 1)));
        out[0] = (float)(t / NK);
        g_ctr = 0;                      // reset for next replay
    }
    for (int j = tid + 1; j < out_size; j += NTH) out[j] = out[0];
}

extern "C" void kernel_launch(void* const* d_in, const int* in_sizes, int n_in,
                              void* d_out, int out_size) {
    const float* base = (const float*)d_in[0];
    const float* mc   = (const float*)d_in[1];
    const int*   seq  = (const int*)d_in[2];
    const int*   sid  = (const int*)d_in[3];

    cudaFuncSetAttribute(cpc_dp4a, cudaFuncAttributeMaxDynamicSharedMemorySize, SMEM_BYTES);

    cpc_dp4a<<<NBLK, NTH, SMEM_BYTES>>>(base, mc, seq, sid, (float*)d_out, out_size);
}

// round 11
// speedup vs baseline: 1.3091x; 1.0073x over previous
#include <cuda_runtime.h>
#include <cstdint>

#define NB 128
#define NT 512
#define NE 128
#define NK 4
#define NNEG 64
#define TILE 32
#define NTH 256
#define NWARP 8
#define NBLK (NB * (NT / TILE))   // 2048 blocks

// smem layout (bytes)
#define NEGT_OFF 0                                 // [32 m][64 n] u32 = 8KB
#define ROWS_OFF (32 * NNEG * 4)                   // 8192: 8 warps x 4 pos x 512B = 16KB
#define POSB_OFF (ROWS_OFF + NWARP * 4 * 512)      // 24576: 8 x 4 x float4
#define SUM_OFF (POSB_OFF + NWARP * 4 * 16)        // 25088
#define SMEM_BYTES (SUM_OFF + 32)

#define QI 25.4f          // 127/5
#define QS (5.0f / 127.0f)

__device__ double g_part[NBLK][NK];   // per-block partials (overwritten every replay)
__device__ unsigned int g_ctr;        // zero-init; last block resets each replay

__device__ __forceinline__ uint32_t q8(float v) {
    int q = __float2int_rn(v * QI);
    q = q > 127 ? 127 : q;
    q = q < -127 ? -127 : q;
    return (uint32_t)q & 255u;
}

__global__ __launch_bounds__(NTH, 4) void cpc_dp4a(
    const float* __restrict__ base,       // [B, T, E]
    const float* __restrict__ mc,         // [B, T, E, K]
    const int*   __restrict__ seq_lens,   // [B]
    const int*   __restrict__ sample_ids, // [B, NNEG]
    float* __restrict__ out, int out_size)
{
    extern __shared__ char smem[];
    const int bid  = blockIdx.x;
    const int b    = bid & (NB - 1);            // LPT: tile-major launch order
    const int t0   = (bid >> 7) * TILE;
    const int tid  = threadIdx.x;
    const int w    = tid >> 5;
    const int lane = tid & 31;
    const int seqlen = seq_lens[b];
    const double LOG65D = 4.174387269895637;
    const float  LOG65  = 4.17438727f;

    if (t0 >= seqlen) {
        // Fully masked tile: every valid position contributes exactly log(65).
        if (tid == 0) {
            #pragma unroll
            for (int i = 0; i < NK; ++i) {
                int cnt = NT - 1 - i - t0;
                if (cnt > TILE) cnt = TILE;
                if (cnt < 0) cnt = 0;
                g_part[bid][i] = (double)cnt * LOG65D;
            }
        }
    } else {
        if (tid < NK) ((float*)(smem + SUM_OFF))[tid] = 0.f;

        // ---- Gather + quantize negatives: NEGT[m][n] (word m*64+n)
        for (int idx = tid; idx < NNEG * 32; idx += NTH) {
            int n = idx >> 5, m = idx & 31;
            float4 v = ((const float4*)(base + (size_t)sample_ids[b * NNEG + n] * NE))[m];
            uint32_t p = q8(v.x) | (q8(v.y) << 8) | (q8(v.z) << 16) | (q8(v.w) << 24);
            *(uint32_t*)(smem + NEGT_OFF + (m * NNEG + n) * 4) = p;
        }
        __syncthreads();

        const float4* mc4 = (const float4*)mc;
        const float S2 = QS * QS;

        // ---- Prep: warp-wide, coalesced, one position at a time (4 per warp).
        // Lane owns e = 4*lane..4*lane+3; builds dp4a word for its chunk locally.
        #pragma unroll 1
        for (int p = 0; p < 4; ++p) {
            const int s = t0 + w * 4 + p;
            if (s >= seqlen) continue;            // warp-uniform

            const float4* src = mc4 + (size_t)(b * NT + s) * NE + 4 * lane;
            float4 c0 = src[0], c1 = src[1], c2 = src[2], c3 = src[3];

            const float4* bp = (const float4*)(base + (size_t)(b * NT + s + 1) * NE) + lane;
            float pacc[4] = {0.f, 0.f, 0.f, 0.f};
            #pragma unroll
            for (int i = 0; i < 4; ++i) {
                if (s + 1 + i < NT) {             // warp-uniform guard
                    float4 bv = bp[(size_t)i * 32];
                    float x0 = (i == 0) ? c0.x : (i == 1) ? c0.y : (i == 2) ? c0.z : c0.w;
                    float x1 = (i == 0) ? c1.x : (i == 1) ? c1.y : (i == 2) ? c1.z : c1.w;
                    float x2 = (i == 0) ? c2.x : (i == 1) ? c2.y : (i == 2) ? c2.z : c2.w;
                    float x3 = (i == 0) ? c3.x : (i == 1) ? c3.y : (i == 2) ? c3.z : c3.w;
                    pacc[i] = x0 * bv.x + x1 * bv.y + x2 * bv.z + x3 * bv.w;
                }
            }
            #pragma unroll
            for (int i = 0; i < 4; ++i) {
                #pragma unroll
                for (int o = 16; o > 0; o >>= 1)
                    pacc[i] += __shfl_xor_sync(0xffffffffu, pacc[i], o);
            }

            int4 wd;
            wd.x = (int)(q8(c0.x) | (q8(c1.x) << 8) | (q8(c2.x) << 16) | (q8(c3.x) << 24));
            wd.y = (int)(q8(c0.y) | (q8(c1.y) << 8) | (q8(c2.y) << 16) | (q8(c3.y) << 24));
            wd.z = (int)(q8(c0.z) | (q8(c1.z) << 8) | (q8(c2.z) << 16) | (q8(c3.z) << 24));
            wd.w = (int)(q8(c0.w) | (q8(c1.w) << 8) | (q8(c2.w) << 16) | (q8(c3.w) << 24));
            ((int4*)(smem + ROWS_OFF + (w * 4 + p) * 512))[lane] = wd;   // STS.128
            if (lane == 0)
                *(float4*)(smem + POSB_OFF + (w * 4 + p) * 16) =
                    make_float4(pacc[0], pacc[1], pacc[2], pacc[3]);
        }
        __syncwarp();    // rows/posb produced and consumed by the same warp

        // ---- m-loop: quarter-warp per position, 8 negs per lane
        const int q  = lane >> 3;                 // quarter = position index
        const int ql = lane & 7;
        const uint32_t qmask = 0xffu << (q * 8);  // quarter-local shuffle mask
        const int s  = t0 + w * 4 + q;            // quarter-uniform
        const int4* rowq  = (const int4*)(smem + ROWS_OFF + (w * 4 + q) * 512);
        const int4* negt4 = (const int4*)(smem + NEGT_OFF);

        // Lane owns negs {4ql..4ql+3} (g0) and {32+4ql..32+4ql+3} (g1):
        // per phase-quarter the 8 lanes read contiguous 128B -> conflict-free.
        int acc[8][4];
        #pragma unroll
        for (int n = 0; n < 8; ++n)
            #pragma unroll
            for (int i = 0; i < 4; ++i) acc[n][i] = 0;

        #pragma unroll 8
        for (int m = 0; m < 32; ++m) {
            int4 c  = rowq[m];                    // 1 LDS.128 serves 4 positions
            int4 g0 = negt4[m * 16 + ql];
            int4 g1 = negt4[m * 16 + 8 + ql];
            int gw[8] = {g0.x, g0.y, g0.z, g0.w, g1.x, g1.y, g1.z, g1.w};
            #pragma unroll
            for (int n = 0; n < 8; ++n) {
                acc[n][0] = __dp4a(c.x, gw[n], acc[n][0]);
                acc[n][1] = __dp4a(c.y, gw[n], acc[n][1]);
                acc[n][2] = __dp4a(c.z, gw[n], acc[n][2]);
                acc[n][3] = __dp4a(c.w, gw[n], acc[n][3]);
            }
        }

        // ---- Finish: per-quarter softmax with QUARTER-LOCAL shuffle masks
        // (all 8 lanes of a quarter take identical branches; offsets 4,2,1
        // never cross the quarter boundary)
        float wsum[4] = {0.f, 0.f, 0.f, 0.f};
        if (s < seqlen) {
            float4 pv = *(const float4*)(smem + POSB_OFF + (w * 4 + q) * 16);
            float posv[4] = {pv.x, pv.y, pv.z, pv.w};
            #pragma unroll
            for (int i = 0; i < 4; ++i) {
                if (s < NT - 1 - i) {             // quarter-uniform
                    float se = 0.f;
                    #pragma unroll
                    for (int n = 0; n < 8; ++n)
                        se += __expf((float)acc[n][i] * S2);
                    #pragma unroll
                    for (int o = 4; o > 0; o >>= 1)
                        se += __shfl_xor_sync(qmask, se, o);
                    se += __expf(posv[i]);
                    wsum[i] = __logf(se) - posv[i];
                }
            }
        } else {
            #pragma unroll
            for (int i = 0; i < 4; ++i)
                if (s < NT - 1 - i) wsum[i] = LOG65;
        }

        // Reduce across quarters (unconditional, reconverged, full-warp mask)
        #pragma unroll
        for (int i = 0; i < 4; ++i) {
            wsum[i] += __shfl_xor_sync(0xffffffffu, wsum[i], 8);
            wsum[i] += __shfl_xor_sync(0xffffffffu, wsum[i], 16);
        }
        if (lane == 0) {
            #pragma unroll
            for (int i = 0; i < NK; ++i)
                atomicAdd((float*)(smem + SUM_OFF) + i, wsum[i]);
        }
        __syncthreads();
        if (tid < NK)
            g_part[bid][tid] = (double)((float*)(smem + SUM_OFF))[tid];
    }

    // ---- Last block finalizes
    __threadfence();
    __shared__ unsigned int s_last;
    if (tid == 0) s_last = (atomicAdd(&g_ctr, 1u) == (unsigned)(NBLK - 1));
    __syncthreads();
    if (!s_last) return;

    __shared__ double ssum[NK];
    if (tid < NK) ssum[tid] = 0.0;
    __syncthreads();

    double acc2[NK] = {0.0, 0.0, 0.0, 0.0};
    for (int r = tid; r < NBLK; r += NTH) {
        #pragma unroll
        for (int i = 0; i < NK; ++i) acc2[i] += g_part[r][i];
    }
    #pragma unroll
    for (int i = 0; i < NK; ++i) {
        #pragma unroll
        for (int o = 16; o > 0; o >>= 1)
            acc2[i] += __shfl_xor_sync(0xffffffffu, acc2[i], o);
    }
    if (lane == 0) {
        #pragma unroll
        for (int i = 0; i < NK; ++i) atomicAdd(&ssum[i], acc2[i]);
    }
    __syncthreads();

    if (tid == 0) {
        double t = 0.0;
        #pragma unroll
        for (int i = 0; i < NK; ++i)
            t += ssum[i] / ((double)NB * (double)(NT - (i + 1)));
        out[0] = (float)(t / NK);
        g_ctr = 0;                      // reset for next replay
    }
    for (int j = tid + 1; j < out_size; j += NTH) out[j] = out[0];
}

extern "C" void kernel_launch(void* const* d_in, const int* in_sizes, int n_in,
                              void* d_out, int out_size) {
    const float* base = (const float*)d_in[0];
    const float* mc   = (const float*)d_in[1];
    const int*   seq  = (const int*)d_in[2];
    const int*   sid  = (const int*)d_in[3];

    cudaFuncSetAttribute(cpc_dp4a, cudaFuncAttributeMaxDynamicSharedMemorySize, SMEM_BYTES);

    cpc_dp4a<<<NBLK, NTH, SMEM_BYTES>>>(base, mc, seq, sid, (float*)d_out, out_size);
}